// round 13
// baseline (speedup 1.0000x reference)
#include <cuda_runtime.h>
#include <cuda_fp16.h>
#include <cstdint>
#include <cstddef>

// ---------------------------------------------------------------------------
// Problem constants
// ---------------------------------------------------------------------------
constexpr int NN  = 8192;   // nodes
constexpr int FIN = 256;    // input features
constexpr int HC  = 128;    // fused hidden columns (h1 | h2)

// GEMM tiling (R9-validated): BM=64 BN=128 BK=32, 256 thr, 8 warps (2Mx4N)
constexpr int BM = 64, BN = 128, BKk = 32;
constexpr int KHALF = NN / 2;           // 4096
constexpr int NT = KHALF / BKk;         // 128 iters
constexpr int ROWB = 80;                // padded smem row stride (bytes)
constexpr int OA = 0;
constexpr int OB = BM * ROWB;           // 5120
constexpr int STAGE = OB + BN * ROWB;   // 15360 bytes / stage
constexpr int NSTG = 4;                 // deeper pipeline (B 3 iters ahead)
constexpr int DYN_SMEM = NSTG * STAGE + 256;

constexpr float ASCALE   = 8192.0f;     // exact pow2: adj*ASCALE in (0,1) for fp16
constexpr float ASCALE_I = 1.0f / 8192.0f;

// ---------------------------------------------------------------------------
// Device scratch (allocation-free per harness rules)
// ---------------------------------------------------------------------------
__device__ unsigned short g_bh[HC * NN];    // fts^T fp16 [n][k]
__device__ float g_acc0[NN * HC];           // K-half 0 partial (scaled by 8192)
__device__ float g_acc1[NN * HC];           // K-half 1 partial
__device__ float g_h[NN * HC];              // h1|h2 after bias+PReLU
__device__ float g_part[128 * 64];          // per-slab colsums of h1*msk
__device__ float g_mskpart[128];            // per-slab msk sums
__device__ float g_wc[64];                  // disc_w @ sigmoid(c)
__device__ int   g_epictr;                  // epi completion ticket

// ---------------------------------------------------------------------------
// Helpers (baseline PTX only — compute_103 virtual target safe)
// ---------------------------------------------------------------------------
__device__ __forceinline__ uint32_t smem_u32(const void* p) {
    uint32_t r;
    asm("{ .reg .u64 t; cvta.to.shared.u64 t, %1; cvt.u32.u64 %0, t; }"
        : "=r"(r) : "l"(p));
    return r;
}
__device__ __forceinline__ uint32_t pkhf(float lo, float hi) {
    __half2 h = __floats2half2_rn(lo, hi);
    return *reinterpret_cast<uint32_t*>(&h);
}
__device__ __forceinline__ void sts64(uint32_t addr, uint32_t a, uint32_t b) {
    asm volatile("st.shared.v2.b32 [%0], {%1, %2};"
                 :: "r"(addr), "r"(a), "r"(b) : "memory");
}
__device__ __forceinline__ void ldm4(uint32_t* r, uint32_t addr) {
    asm volatile("ldmatrix.sync.aligned.m8n8.x4.shared.b16 {%0,%1,%2,%3}, [%4];"
                 : "=r"(r[0]), "=r"(r[1]), "=r"(r[2]), "=r"(r[3]) : "r"(addr));
}
__device__ __forceinline__ void mma16816(float* c, const uint32_t* a,
                                         uint32_t b0, uint32_t b1) {
    asm volatile(
        "mma.sync.aligned.m16n8k16.row.col.f32.f16.f16.f32 "
        "{%0,%1,%2,%3}, {%4,%5,%6,%7}, {%8,%9}, {%0,%1,%2,%3};"
        : "+f"(c[0]), "+f"(c[1]), "+f"(c[2]), "+f"(c[3])
        : "r"(a[0]), "r"(a[1]), "r"(a[2]), "r"(a[3]), "r"(b0), "r"(b1));
}
__device__ __forceinline__ void cpa16(uint32_t dst, const void* src) {
    asm volatile("cp.async.cg.shared.global [%0], [%1], 16;"
                 :: "r"(dst), "l"(src));
}
__device__ __forceinline__ void cp_commit() {
    asm volatile("cp.async.commit_group;" ::: "memory");
}
__device__ __forceinline__ void cp_wait2() {
    asm volatile("cp.async.wait_group 2;" ::: "memory");
}

// ---------------------------------------------------------------------------
// Kernel 1: fts = seq@W^T (both seqs); emit fp16 TRANSPOSED [n][k].
// Also resets the epi ticket (stream-ordered before epi_colsum).
// ---------------------------------------------------------------------------
__global__ void __launch_bounds__(128) fts_kernel(
    const float* __restrict__ seq1, const float* __restrict__ seq2,
    const float* __restrict__ fcw) {
    __shared__ float wt[64][64];    // transposed fc_w chunk [f_local][h]
    __shared__ float s1[16][64];
    __shared__ float s2[16][64];

    if (blockIdx.x == 0 && threadIdx.x == 0) g_epictr = 0;

    const int tid = threadIdx.x;
    const int m0 = blockIdx.x * 16;
    const int jh = tid & 63;

    float acc[16];
#pragma unroll
    for (int r = 0; r < 16; ++r) acc[r] = 0.f;

    for (int fc = 0; fc < 4; ++fc) {
        const int f0 = fc * 64;
        __syncthreads();
        {
            const int row = tid & 63, half = tid >> 6;
#pragma unroll
            for (int p = 0; p < 8; ++p) {
                const int c = half * 8 + p;
                float4 v = *(const float4*)&fcw[row * FIN + f0 + c * 4];
                wt[c * 4 + 0][row] = v.x;
                wt[c * 4 + 1][row] = v.y;
                wt[c * 4 + 2][row] = v.z;
                wt[c * 4 + 3][row] = v.w;
            }
        }
#pragma unroll
        for (int p = 0; p < 2; ++p) {
            const int idx = tid + 128 * p;
            const int r = idx >> 4, c4 = idx & 15;
            *(float4*)&s1[r][c4 * 4] = *(const float4*)&seq1[(size_t)(m0 + r) * FIN + f0 + c4 * 4];
            *(float4*)&s2[r][c4 * 4] = *(const float4*)&seq2[(size_t)(m0 + r) * FIN + f0 + c4 * 4];
        }
        __syncthreads();

        const float (*sp)[64] = (tid < 64) ? s1 : s2;
#pragma unroll 4
        for (int f = 0; f < 64; ++f) {
            const float wv = wt[f][jh];
#pragma unroll
            for (int r = 0; r < 16; ++r) acc[r] += sp[r][f] * wv;
        }
    }

#pragma unroll
    for (int r = 0; r < 16; r += 2) {
        const uint32_t h = pkhf(acc[r], acc[r + 1]);
        *(uint32_t*)(g_bh + (size_t)tid * NN + m0 + r) = h;
    }
}

// ---------------------------------------------------------------------------
// Kernel 2 (dominant): fp16 HMMA GEMM, R9 shape, DEEPER pipeline.
// Per iter: BCP(t+3);commit -> ALDG(t+3) -> COMPUTE(t) -> ASTS(t+1)
//           -> cp_wait2 -> sync.       (B 3 ahead, A reg-ring 3 deep)
// CTA = (mi, kh): rows [mi*64, +64), K-half kh; 8 warps (2M x 4N).
// ---------------------------------------------------------------------------
__global__ void __launch_bounds__(256, 2)
gemm_mma(const float* __restrict__ adj) {
    extern __shared__ char dyn[];
    const uint32_t sbase = (smem_u32(dyn) + 127u) & ~127u;

    const int tid = threadIdx.x;
    const int wid = tid >> 5;
    const int lane = tid & 31;
    const int mi = blockIdx.x >> 1;
    const int kh = blockIdx.x & 1;
    const int m0 = mi * BM;
    const size_t kbase = (size_t)kh * KHALF;

    const int wm = (wid & 1) * 32;      // warp M offset (0/32)
    const int wn = (wid >> 1) * 32;     // warp N offset (0..96)

    // coalesced producer mappings (validated R6-R9)
    const int arow = tid >> 3;              // 0..31
    const float* aptr = adj + (size_t)(m0 + arow) * NN + kbase + (tid & 7) * 4;
    const uint32_t a_sts = (uint32_t)(arow * ROWB + (tid & 7) * 8);
    const int brow = tid >> 2;              // 0..63
    const unsigned short* bptr = g_bh + (size_t)brow * NN + kbase + (tid & 3) * 8;
    const uint32_t b_sts = (uint32_t)(brow * ROWB + (tid & 3) * 16);

    // ldmatrix per-lane offsets (fragment layout validated R4-R9)
    const uint32_t a_ld = (uint32_t)((wm + (lane & 15)) * ROWB + (lane >> 4) * 16);
    const uint32_t b_ld = (uint32_t)((wn + ((lane >> 4) << 3) + (lane & 7)) * ROWB
                                     + ((lane >> 3) & 1) * 16);

    float acc[2][4][4];
#pragma unroll
    for (int i = 0; i < 2; ++i)
#pragma unroll
        for (int j = 0; j < 4; ++j)
#pragma unroll
            for (int q = 0; q < 4; ++q) acc[i][j][q] = 0.f;

    float4 av[3][2];    // A LDG register ring, 3 deep (set = t mod 3)

    auto BCP = [&](int t) {     // cp.async B chunk t into stage t%NSTG
        const uint32_t st = sbase + (t % NSTG) * STAGE;
        const unsigned short* bp = bptr + (size_t)t * BKk;
#pragma unroll
        for (int p = 0; p < 2; ++p)
            cpa16(st + OB + b_sts + p * (64 * ROWB), bp + (size_t)p * 64 * NN);
    };
    auto ALDG = [&](int t, int set) {
        const float* ap = aptr + (size_t)t * BKk;
#pragma unroll
        for (int p = 0; p < 2; ++p)
            av[set][p] = *(const float4*)(ap + (size_t)p * 32 * NN);
    };
    auto ASTS = [&](int t, int set) {
        const uint32_t st = sbase + (t % NSTG) * STAGE;
#pragma unroll
        for (int p = 0; p < 2; ++p) {
            uint32_t w0 = pkhf(av[set][p].x * ASCALE, av[set][p].y * ASCALE);
            uint32_t w1 = pkhf(av[set][p].z * ASCALE, av[set][p].w * ASCALE);
            sts64(st + OA + a_sts + p * (32 * ROWB), w0, w1);
        }
    };
    auto COMPUTE = [&](int t) {
        const uint32_t st = sbase + (t % NSTG) * STAGE;
#pragma unroll
        for (int ks = 0; ks < 2; ++ks) {
            uint32_t ah[2][4];
            ldm4(ah[0], st + OA + a_ld + ks * 32);
            ldm4(ah[1], st + OA + a_ld + 16 * ROWB + ks * 32);
#pragma unroll
            for (int jp = 0; jp < 2; ++jp) {
                uint32_t b[4];
                ldm4(b, st + OB + b_ld + jp * (16 * ROWB) + ks * 32);
                mma16816(acc[0][2 * jp],     ah[0], b[0], b[1]);
                mma16816(acc[0][2 * jp + 1], ah[0], b[2], b[3]);
                mma16816(acc[1][2 * jp],     ah[1], b[0], b[1]);
                mma16816(acc[1][2 * jp + 1], ah[1], b[2], b[3]);
            }
        }
    };

    // prologue: B chunks 0,1,2 committed (1 group each); A 0,1,2 in the ring;
    // A stage0 stored. cp_wait2 -> chunk 0 complete; sync publishes.
    BCP(0); cp_commit();
    BCP(1); cp_commit();
    BCP(2); cp_commit();
    ALDG(0, 0);
    ALDG(1, 1);
    ALDG(2, 2);
    ASTS(0, 0);
    cp_wait2();
    __syncthreads();

    int s0 = 0;     // = t mod 3
    for (int t = 0; t < NT; ++t) {
        if (t + 3 < NT) BCP(t + 3);
        cp_commit();                            // uniform commit (may be empty)
        if (t + 3 < NT) ALDG(t + 3, s0);        // set t%3 free (consumed at t)
        COMPUTE(t);                             // stage t resident
        if (t + 1 < NT) ASTS(t + 1, s0 == 2 ? 0 : s0 + 1);
        cp_wait2();                             // chunk t+1 copies complete
        __syncthreads();                        // publish everyone's chunk t+1
        s0 = (s0 == 2) ? 0 : s0 + 1;
    }

    // epilogue: write raw (scaled) partials
    float* gacc = (kh ? g_acc1 : g_acc0);
    const int r0 = m0 + wm + (lane >> 2);
    const int cb = wn + (lane & 3) * 2;
#pragma unroll
    for (int i = 0; i < 2; ++i) {
#pragma unroll
        for (int j = 0; j < 4; ++j) {
            const int rr = r0 + i * 16;
            const int col = cb + j * 8;
            *(float2*)&gacc[(size_t)rr * HC + col] =
                make_float2(acc[i][j][0], acc[i][j][1]);
            *(float2*)&gacc[(size_t)(rr + 8) * HC + col] =
                make_float2(acc[i][j][2], acc[i][j][3]);
        }
    }
}

// ---------------------------------------------------------------------------
// Kernel 3: h = PReLU((acc0+acc1)/8192 + bias) + per-slab colsums; the LAST
// block to finish also computes wc = disc_w @ sigmoid(colsum/msksum) inline
// (fixed-order summation -> deterministic). grid 128 x 256.
// ---------------------------------------------------------------------------
__global__ void __launch_bounds__(256) epi_colsum(
    const float* __restrict__ bias, const float* __restrict__ alphap,
    const float* __restrict__ msk, const float* __restrict__ disc_w) {
    __shared__ float sp[2][64];
    __shared__ float sm[64];
    __shared__ int last_s;
    const int b = blockIdx.x, tid = threadIdx.x;
    const int c = tid & 127, rg = tid >> 7;
    const int base = b * 64;
    const float alpha = __ldg(alphap);
    const float bi = __ldg(&bias[c & 63]);

    float csum = 0.f;
#pragma unroll 4
    for (int i = 0; i < 32; ++i) {
        const int n = base + rg + 2 * i;
        const size_t idx = (size_t)n * HC + c;
        float v = (g_acc0[idx] + g_acc1[idx]) * ASCALE_I + bi;
        v = v > 0.f ? v : alpha * v;
        g_h[idx] = v;
        csum += msk[n] * v;     // only meaningful for c<64 (h1)
    }
    if (c < 64) sp[rg][c] = csum;
    if (tid < 64) sm[tid] = msk[base + tid];
    __syncthreads();

    if (tid < 64) g_part[b * 64 + tid] = sp[0][tid] + sp[1][tid];
    if (tid < 32) {
        float m = sm[tid] + sm[tid + 32];
#pragma unroll
        for (int o = 16; o; o >>= 1) m += __shfl_down_sync(0xffffffffu, m, o);
        if (tid == 0) g_mskpart[b] = m;
    }
    __syncthreads();

    // completion ticket: last block computes wc
    if (tid == 0) {
        __threadfence();
        last_s = (atomicAdd(&g_epictr, 1) == gridDim.x - 1);
    }
    __syncthreads();
    if (!last_s) return;

    __shared__ float red[4][64];
    __shared__ float cvec[64];
    __shared__ float msum_s;
    {
        const int g = tid >> 6, col = tid & 63;
        float s = 0.f;
#pragma unroll
        for (int bb = 0; bb < 32; ++bb) s += g_part[(g * 32 + bb) * 64 + col];
        red[g][col] = s;
        if (tid < 32) {
            float m = 0.f;
#pragma unroll
            for (int bb = 0; bb < 4; ++bb) m += g_mskpart[tid + bb * 32];
#pragma unroll
            for (int o = 16; o; o >>= 1) m += __shfl_down_sync(0xffffffffu, m, o);
            if (tid == 0) msum_s = m;
        }
        __syncthreads();
        if (tid < 64) {
            float cv = (red[0][tid] + red[1][tid] + red[2][tid] + red[3][tid]) / msum_s;
            cvec[tid] = 1.f / (1.f + expf(-cv));
        }
        __syncthreads();
        const int j = tid >> 2, q = tid & 3;
        float r = 0.f;
#pragma unroll
        for (int k = 0; k < 16; ++k)
            r += disc_w[j * 64 + q * 16 + k] * cvec[q * 16 + k];
        r += __shfl_down_sync(0xffffffffu, r, 2);
        r += __shfl_down_sync(0xffffffffu, r, 1);
        if (q == 0) g_wc[j] = r;
    }
}

// ---------------------------------------------------------------------------
// Kernel 4: out[n] = h1[n,:].wc + b ; out[N+n] = h2[n,:].wc + b
// ---------------------------------------------------------------------------
__global__ void __launch_bounds__(256) scores(const float* __restrict__ db,
                                              float* __restrict__ out) {
    const int warp = threadIdx.x >> 5, lane = threadIdx.x & 31;
    const int n = blockIdx.x * 8 + warp;
    const float2* hp = (const float2*)(g_h + (size_t)n * HC);
    const float2 w2 = ((const float2*)g_wc)[lane];
    const float2 v1 = hp[lane];
    const float2 v2 = hp[32 + lane];
    float s1 = v1.x * w2.x + v1.y * w2.y;
    float s2 = v2.x * w2.x + v2.y * w2.y;
#pragma unroll
    for (int o = 16; o; o >>= 1) {
        s1 += __shfl_down_sync(0xffffffffu, s1, o);
        s2 += __shfl_down_sync(0xffffffffu, s2, o);
    }
    if (lane == 0) {
        const float bb = __ldg(db);
        out[n] = s1 + bb;
        out[NN + n] = s2 + bb;
    }
}

// ---------------------------------------------------------------------------
// Inputs: seq1, seq2, adj, msk, fc_w, gcn_bias, prelu_alpha, disc_w, disc_b
// Output: [1, 2N] float32
// ---------------------------------------------------------------------------
extern "C" void kernel_launch(void* const* d_in, const int* in_sizes, int n_in,
                              void* d_out, int out_size) {
    const float* seq1  = (const float*)d_in[0];
    const float* seq2  = (const float*)d_in[1];
    const float* adj   = (const float*)d_in[2];
    const float* msk   = (const float*)d_in[3];
    const float* fcw   = (const float*)d_in[4];
    const float* gbias = (const float*)d_in[5];
    const float* alpha = (const float*)d_in[6];
    const float* discw = (const float*)d_in[7];
    const float* discb = (const float*)d_in[8];
    float* out = (float*)d_out;

    cudaFuncSetAttribute(gemm_mma, cudaFuncAttributeMaxDynamicSharedMemorySize,
                         DYN_SMEM);

    fts_kernel<<<NN / 16, 128>>>(seq1, seq2, fcw);
    gemm_mma<<<(NN / BM) * 2, 256, DYN_SMEM>>>(adj);
    epi_colsum<<<128, 256>>>(gbias, alpha, msk, discw);
    scores<<<NN / 8, 256>>>(discb, out);
}

// round 14
// speedup vs baseline: 1.3829x; 1.3829x over previous
#include <cuda_runtime.h>
#include <cuda_fp16.h>
#include <cstdint>
#include <cstddef>

// ---------------------------------------------------------------------------
// Problem constants
// ---------------------------------------------------------------------------
constexpr int NN  = 8192;   // nodes
constexpr int FIN = 256;    // input features
constexpr int HC  = 128;    // fused hidden columns (h1 | h2)

// GEMM tiling (R9-validated, DO NOT TOUCH): BM=64 BN=128 BK=32, 256 thr
constexpr int BM = 64, BN = 128, BKk = 32;
constexpr int KHALF = NN / 2;           // 4096
constexpr int NT = KHALF / BKk;         // 128 iters
constexpr int ROWB = 80;                // padded smem row stride (bytes)
constexpr int OA = 0;
constexpr int OB = BM * ROWB;           // 5120
constexpr int STAGE = OB + BN * ROWB;   // 15360 bytes / stage
constexpr int NSTG = 3;
constexpr int DYN_SMEM = NSTG * STAGE + 256;

constexpr float ASCALE   = 8192.0f;     // exact pow2: adj*ASCALE in (0,1) for fp16
constexpr float ASCALE_I = 1.0f / 8192.0f;

// ---------------------------------------------------------------------------
// Device scratch (allocation-free per harness rules)
// ---------------------------------------------------------------------------
__device__ unsigned short g_bh[HC * NN];    // fts^T fp16 [n][k]
__device__ float g_acc0[NN * HC];           // K-half 0 partial (scaled by 8192)
__device__ float g_acc1[NN * HC];           // K-half 1 partial
__device__ float g_h[NN * HC];              // h1|h2 after bias+PReLU
__device__ float g_part[128 * 64];          // per-slab colsums of h1*msk
__device__ float g_mskpart[128];            // per-slab msk sums
__device__ float g_wc[64];                  // disc_w @ sigmoid(c)
__device__ int   g_epictr;                  // epi completion ticket

// ---------------------------------------------------------------------------
// Helpers (baseline PTX only — compute_103 virtual target safe)
// ---------------------------------------------------------------------------
using u64 = unsigned long long;

__device__ __forceinline__ uint32_t smem_u32(const void* p) {
    uint32_t r;
    asm("{ .reg .u64 t; cvta.to.shared.u64 t, %1; cvt.u32.u64 %0, t; }"
        : "=r"(r) : "l"(p));
    return r;
}
__device__ __forceinline__ uint32_t pkhf(float lo, float hi) {
    __half2 h = __floats2half2_rn(lo, hi);
    return *reinterpret_cast<uint32_t*>(&h);
}
__device__ __forceinline__ u64 pk2(float x, float y) {
    u64 r; asm("mov.b64 %0, {%1,%2};" : "=l"(r) : "f"(x), "f"(y)); return r;
}
__device__ __forceinline__ float2 unpk(u64 v) {
    float2 r; asm("mov.b64 {%0,%1}, %2;" : "=f"(r.x), "=f"(r.y) : "l"(v)); return r;
}
// Packed dual-FMA on the fma pipe (PTX-only form)
__device__ __forceinline__ void fma2(u64& d, u64 a, u64 b) {
    asm("fma.rn.f32x2 %0, %1, %2, %0;" : "+l"(d) : "l"(a), "l"(b));
}
__device__ __forceinline__ void sts64(uint32_t addr, uint32_t a, uint32_t b) {
    asm volatile("st.shared.v2.b32 [%0], {%1, %2};"
                 :: "r"(addr), "r"(a), "r"(b) : "memory");
}
__device__ __forceinline__ void ldm4(uint32_t* r, uint32_t addr) {
    asm volatile("ldmatrix.sync.aligned.m8n8.x4.shared.b16 {%0,%1,%2,%3}, [%4];"
                 : "=r"(r[0]), "=r"(r[1]), "=r"(r[2]), "=r"(r[3]) : "r"(addr));
}
__device__ __forceinline__ void mma16816(float* c, const uint32_t* a,
                                         uint32_t b0, uint32_t b1) {
    asm volatile(
        "mma.sync.aligned.m16n8k16.row.col.f32.f16.f16.f32 "
        "{%0,%1,%2,%3}, {%4,%5,%6,%7}, {%8,%9}, {%0,%1,%2,%3};"
        : "+f"(c[0]), "+f"(c[1]), "+f"(c[2]), "+f"(c[3])
        : "r"(a[0]), "r"(a[1]), "r"(a[2]), "r"(a[3]), "r"(b0), "r"(b1));
}
__device__ __forceinline__ void cpa16(uint32_t dst, const void* src) {
    asm volatile("cp.async.cg.shared.global [%0], [%1], 16;"
                 :: "r"(dst), "l"(src));
}
__device__ __forceinline__ void cp_commit() {
    asm volatile("cp.async.commit_group;" ::: "memory");
}
__device__ __forceinline__ void cp_wait1() {
    asm volatile("cp.async.wait_group 1;" ::: "memory");
}

// ---------------------------------------------------------------------------
// Kernel 1: fts = seq@W^T (both seqs); emit fp16 TRANSPOSED [n][k].
// f32x2-packed compute: each thread owns 4 rows x 4 cols. Also resets the
// epi completion ticket (stream-ordered before epi_colsum).
// ---------------------------------------------------------------------------
__global__ void __launch_bounds__(128) fts_kernel(
    const float* __restrict__ seq1, const float* __restrict__ seq2,
    const float* __restrict__ fcw) {
    __shared__ float wt[64][64];    // transposed fc_w chunk [f_local][h]
    __shared__ float s1[16][64];
    __shared__ float s2[16][64];

    if (blockIdx.x == 0 && threadIdx.x == 0) g_epictr = 0;

    const int tid = threadIdx.x;
    const int m0 = blockIdx.x * 16;
    const int id = tid & 63;
    const int cg = id & 15;         // col group: cols 4cg..4cg+3
    const int rg = id >> 4;         // row group: rows 4rg..4rg+3
    const int j0 = cg * 4;
    const int r0 = rg * 4;
    const int nbase = (tid < 64) ? 0 : 64;

    u64 acc2[4][2];                 // [row i][col pair]: cols (j0,j0+1),(j0+2,j0+3)
#pragma unroll
    for (int i = 0; i < 4; ++i) { acc2[i][0] = 0ull; acc2[i][1] = 0ull; }

    for (int fc = 0; fc < 4; ++fc) {
        const int f0 = fc * 64;
        __syncthreads();
        {
            const int row = tid & 63, half = tid >> 6;
#pragma unroll
            for (int p = 0; p < 8; ++p) {
                const int c = half * 8 + p;
                float4 v = *(const float4*)&fcw[row * FIN + f0 + c * 4];
                wt[c * 4 + 0][row] = v.x;
                wt[c * 4 + 1][row] = v.y;
                wt[c * 4 + 2][row] = v.z;
                wt[c * 4 + 3][row] = v.w;
            }
        }
#pragma unroll
        for (int p = 0; p < 2; ++p) {
            const int idx = tid + 128 * p;
            const int r = idx >> 4, c4 = idx & 15;
            *(float4*)&s1[r][c4 * 4] = *(const float4*)&seq1[(size_t)(m0 + r) * FIN + f0 + c4 * 4];
            *(float4*)&s2[r][c4 * 4] = *(const float4*)&seq2[(size_t)(m0 + r) * FIN + f0 + c4 * 4];
        }
        __syncthreads();

        const float (*sp)[64] = (tid < 64) ? s1 : s2;
#pragma unroll 4
        for (int f = 0; f < 64; ++f) {
            const float2 wa = *(const float2*)&wt[f][j0];
            const float2 wb = *(const float2*)&wt[f][j0 + 2];
            const u64 w01 = pk2(wa.x, wa.y);
            const u64 w23 = pk2(wb.x, wb.y);
#pragma unroll
            for (int i = 0; i < 4; ++i) {
                const float a = sp[r0 + i][f];
                const u64 aa = pk2(a, a);
                fma2(acc2[i][0], aa, w01);
                fma2(acc2[i][1], aa, w23);
            }
        }
    }

    // register transpose -> fp16 pack -> g_bh[n][k] (n = nbase+j, k = m0+r0+i)
    float v[4][4];                  // [row i][col jc]
#pragma unroll
    for (int i = 0; i < 4; ++i) {
        const float2 p0 = unpk(acc2[i][0]);
        const float2 p1 = unpk(acc2[i][1]);
        v[i][0] = p0.x; v[i][1] = p0.y; v[i][2] = p1.x; v[i][3] = p1.y;
    }
#pragma unroll
    for (int jc = 0; jc < 4; ++jc) {
        const int n = nbase + j0 + jc;
        uint2 h;
        h.x = pkhf(v[0][jc], v[1][jc]);
        h.y = pkhf(v[2][jc], v[3][jc]);
        *(uint2*)(g_bh + (size_t)n * NN + m0 + r0) = h;
    }
}

// ---------------------------------------------------------------------------
// Kernel 2 (dominant): fp16 HMMA GEMM — EXACT R9 configuration (validated
// fastest: 3 stages, wait-before-barrier, 8 warps 2Mx4N, 32x32 warp tiles).
// ---------------------------------------------------------------------------
__global__ void __launch_bounds__(256, 2)
gemm_mma(const float* __restrict__ adj) {
    extern __shared__ char dyn[];
    const uint32_t sbase = (smem_u32(dyn) + 127u) & ~127u;

    const int tid = threadIdx.x;
    const int wid = tid >> 5;
    const int lane = tid & 31;
    const int mi = blockIdx.x >> 1;
    const int kh = blockIdx.x & 1;
    const int m0 = mi * BM;
    const size_t kbase = (size_t)kh * KHALF;

    const int wm = (wid & 1) * 32;      // warp M offset (0/32)
    const int wn = (wid >> 1) * 32;     // warp N offset (0..96)

    const int arow = tid >> 3;              // 0..31
    const float* aptr = adj + (size_t)(m0 + arow) * NN + kbase + (tid & 7) * 4;
    const uint32_t a_sts = (uint32_t)(arow * ROWB + (tid & 7) * 8);
    const int brow = tid >> 2;              // 0..63
    const unsigned short* bptr = g_bh + (size_t)brow * NN + kbase + (tid & 3) * 8;
    const uint32_t b_sts = (uint32_t)(brow * ROWB + (tid & 3) * 16);

    const uint32_t a_ld = (uint32_t)((wm + (lane & 15)) * ROWB + (lane >> 4) * 16);
    const uint32_t b_ld = (uint32_t)((wn + ((lane >> 4) << 3) + (lane & 7)) * ROWB
                                     + ((lane >> 3) & 1) * 16);

    float acc[2][4][4];
#pragma unroll
    for (int i = 0; i < 2; ++i)
#pragma unroll
        for (int j = 0; j < 4; ++j)
#pragma unroll
            for (int q = 0; q < 4; ++q) acc[i][j][q] = 0.f;

    float4 av[2][2];

    auto BCP = [&](int t) {
        const uint32_t st = sbase + (t % NSTG) * STAGE;
        const unsigned short* bp = bptr + (size_t)t * BKk;
#pragma unroll
        for (int p = 0; p < 2; ++p)
            cpa16(st + OB + b_sts + p * (64 * ROWB), bp + (size_t)p * 64 * NN);
    };
    auto ALDG = [&](int t, int set) {
        const float* ap = aptr + (size_t)t * BKk;
#pragma unroll
        for (int p = 0; p < 2; ++p)
            av[set][p] = *(const float4*)(ap + (size_t)p * 32 * NN);
    };
    auto ASTS = [&](int t, int set) {
        const uint32_t st = sbase + (t % NSTG) * STAGE;
#pragma unroll
        for (int p = 0; p < 2; ++p) {
            uint32_t w0 = pkhf(av[set][p].x * ASCALE, av[set][p].y * ASCALE);
            uint32_t w1 = pkhf(av[set][p].z * ASCALE, av[set][p].w * ASCALE);
            sts64(st + OA + a_sts + p * (32 * ROWB), w0, w1);
        }
    };
    auto COMPUTE = [&](int t) {
        const uint32_t st = sbase + (t % NSTG) * STAGE;
#pragma unroll
        for (int ks = 0; ks < 2; ++ks) {
            uint32_t ah[2][4];
            ldm4(ah[0], st + OA + a_ld + ks * 32);
            ldm4(ah[1], st + OA + a_ld + 16 * ROWB + ks * 32);
#pragma unroll
            for (int jp = 0; jp < 2; ++jp) {
                uint32_t b[4];
                ldm4(b, st + OB + b_ld + jp * (16 * ROWB) + ks * 32);
                mma16816(acc[0][2 * jp],     ah[0], b[0], b[1]);
                mma16816(acc[0][2 * jp + 1], ah[0], b[2], b[3]);
                mma16816(acc[1][2 * jp],     ah[1], b[0], b[1]);
                mma16816(acc[1][2 * jp + 1], ah[1], b[2], b[3]);
            }
        }
    };

    BCP(0); cp_commit();
    BCP(1); cp_commit();
    ALDG(0, 0);
    ALDG(1, 1);
    ASTS(0, 0);
    cp_wait1();
    __syncthreads();

    int cur = 1;
    for (int t = 0; t < NT; ++t) {
        if (t + 2 < NT) BCP(t + 2);
        cp_commit();
        if (t + 2 < NT) ALDG(t + 2, cur ^ 1);
        COMPUTE(t);
        if (t + 1 < NT) ASTS(t + 1, cur);
        cp_wait1();
        __syncthreads();
        cur ^= 1;
    }

    float* gacc = (kh ? g_acc1 : g_acc0);
    const int r0 = m0 + wm + (lane >> 2);
    const int cb = wn + (lane & 3) * 2;
#pragma unroll
    for (int i = 0; i < 2; ++i) {
#pragma unroll
        for (int j = 0; j < 4; ++j) {
            const int rr = r0 + i * 16;
            const int col = cb + j * 8;
            *(float2*)&gacc[(size_t)rr * HC + col] =
                make_float2(acc[i][j][0], acc[i][j][1]);
            *(float2*)&gacc[(size_t)(rr + 8) * HC + col] =
                make_float2(acc[i][j][2], acc[i][j][3]);
        }
    }
}

// ---------------------------------------------------------------------------
// Kernel 3: h = PReLU((acc0+acc1)/8192 + bias) + per-slab colsums; the LAST
// block also computes wc = disc_w @ sigmoid(colsum/msksum) inline
// (fixed-order summation -> deterministic). Validated in R13. grid 128x256.
// ---------------------------------------------------------------------------
__global__ void __launch_bounds__(256) epi_colsum(
    const float* __restrict__ bias, const float* __restrict__ alphap,
    const float* __restrict__ msk, const float* __restrict__ disc_w) {
    __shared__ float sp[2][64];
    __shared__ float sm[64];
    __shared__ int last_s;
    const int b = blockIdx.x, tid = threadIdx.x;
    const int c = tid & 127, rg = tid >> 7;
    const int base = b * 64;
    const float alpha = __ldg(alphap);
    const float bi = __ldg(&bias[c & 63]);

    float csum = 0.f;
#pragma unroll 4
    for (int i = 0; i < 32; ++i) {
        const int n = base + rg + 2 * i;
        const size_t idx = (size_t)n * HC + c;
        float v = (g_acc0[idx] + g_acc1[idx]) * ASCALE_I + bi;
        v = v > 0.f ? v : alpha * v;
        g_h[idx] = v;
        csum += msk[n] * v;     // only meaningful for c<64 (h1)
    }
    if (c < 64) sp[rg][c] = csum;
    if (tid < 64) sm[tid] = msk[base + tid];
    __syncthreads();

    if (tid < 64) g_part[b * 64 + tid] = sp[0][tid] + sp[1][tid];
    if (tid < 32) {
        float m = sm[tid] + sm[tid + 32];
#pragma unroll
        for (int o = 16; o; o >>= 1) m += __shfl_down_sync(0xffffffffu, m, o);
        if (tid == 0) g_mskpart[b] = m;
    }
    __syncthreads();

    if (tid == 0) {
        __threadfence();
        last_s = (atomicAdd(&g_epictr, 1) == gridDim.x - 1);
    }
    __syncthreads();
    if (!last_s) return;

    __shared__ float red[4][64];
    __shared__ float cvec[64];
    __shared__ float msum_s;
    {
        const int g = tid >> 6, col = tid & 63;
        float s = 0.f;
#pragma unroll
        for (int bb = 0; bb < 32; ++bb) s += g_part[(g * 32 + bb) * 64 + col];
        red[g][col] = s;
        if (tid < 32) {
            float m = 0.f;
#pragma unroll
            for (int bb = 0; bb < 4; ++bb) m += g_mskpart[tid + bb * 32];
#pragma unroll
            for (int o = 16; o; o >>= 1) m += __shfl_down_sync(0xffffffffu, m, o);
            if (tid == 0) msum_s = m;
        }
        __syncthreads();
        if (tid < 64) {
            float cv = (red[0][tid] + red[1][tid] + red[2][tid] + red[3][tid]) / msum_s;
            cvec[tid] = 1.f / (1.f + expf(-cv));
        }
        __syncthreads();
        const int j = tid >> 2, q = tid & 3;
        float r = 0.f;
#pragma unroll
        for (int k = 0; k < 16; ++k)
            r += disc_w[j * 64 + q * 16 + k] * cvec[q * 16 + k];
        r += __shfl_down_sync(0xffffffffu, r, 2);
        r += __shfl_down_sync(0xffffffffu, r, 1);
        if (q == 0) g_wc[j] = r;
    }
}

// ---------------------------------------------------------------------------
// Kernel 4: out[n] = h1[n,:].wc + b ; out[N+n] = h2[n,:].wc + b
// ---------------------------------------------------------------------------
__global__ void __launch_bounds__(256) scores(const float* __restrict__ db,
                                              float* __restrict__ out) {
    const int warp = threadIdx.x >> 5, lane = threadIdx.x & 31;
    const int n = blockIdx.x * 8 + warp;
    const float2* hp = (const float2*)(g_h + (size_t)n * HC);
    const float2 w2 = ((const float2*)g_wc)[lane];
    const float2 v1 = hp[lane];
    const float2 v2 = hp[32 + lane];
    float s1 = v1.x * w2.x + v1.y * w2.y;
    float s2 = v2.x * w2.x + v2.y * w2.y;
#pragma unroll
    for (int o = 16; o; o >>= 1) {
        s1 += __shfl_down_sync(0xffffffffu, s1, o);
        s2 += __shfl_down_sync(0xffffffffu, s2, o);
    }
    if (lane == 0) {
        const float bb = __ldg(db);
        out[n] = s1 + bb;
        out[NN + n] = s2 + bb;
    }
}

// ---------------------------------------------------------------------------
// Inputs: seq1, seq2, adj, msk, fc_w, gcn_bias, prelu_alpha, disc_w, disc_b
// Output: [1, 2N] float32
// ---------------------------------------------------------------------------
extern "C" void kernel_launch(void* const* d_in, const int* in_sizes, int n_in,
                              void* d_out, int out_size) {
    const float* seq1  = (const float*)d_in[0];
    const float* seq2  = (const float*)d_in[1];
    const float* adj   = (const float*)d_in[2];
    const float* msk   = (const float*)d_in[3];
    const float* fcw   = (const float*)d_in[4];
    const float* gbias = (const float*)d_in[5];
    const float* alpha = (const float*)d_in[6];
    const float* discw = (const float*)d_in[7];
    const float* discb = (const float*)d_in[8];
    float* out = (float*)d_out;

    cudaFuncSetAttribute(gemm_mma, cudaFuncAttributeMaxDynamicSharedMemorySize,
                         DYN_SMEM);

    fts_kernel<<<NN / 16, 128>>>(seq1, seq2, fcw);
    gemm_mma<<<(NN / BM) * 2, 256, DYN_SMEM>>>(adj);
    epi_colsum<<<128, 256>>>(gbias, alpha, msk, discw);
    scores<<<NN / 8, 256>>>(discb, out);
}